// round 4
// baseline (speedup 1.0000x reference)
#include <cuda_runtime.h>
#include <cstdint>

#define BATCH 8
#define CCH   512
#define HH    64
#define PIX   4096                      // HH*HH
#define NELEM (BATCH * CCH * PIX)       // 16,777,216

// Scratch (static device globals — no runtime allocation)
__device__ float g_fopt[NELEM];
__device__ float g_fsar[NELEM];
__device__ float g_sopt[NELEM];
__device__ float g_ssar[NELEM];

// ---------------------------------------------------------------------------
// Kernel 1: 1x1 conv as GEMM.  F[b,o,p] = sum_c W[o,c] * X[b,c,p]
// Tile 64(M) x 64(N) x 16(K), 256 threads, 4x4 microtile per thread.
// ---------------------------------------------------------------------------
__global__ __launch_bounds__(256) void conv1x1_kernel(
    const float* __restrict__ X,   // [B, C, P]
    const float* __restrict__ Wm,  // [C_out, C_in]
    float* __restrict__ F)         // [B, C, P]
{
    __shared__ float As[64][17];   // As[m][k], padded to kill bank conflicts
    __shared__ float Bs[16][64];   // Bs[k][n]

    const int b  = blockIdx.z;
    const int m0 = blockIdx.y * 64;
    const int n0 = blockIdx.x * 64;
    const int tid = threadIdx.x;
    const int ty4 = (tid >> 4) * 4;    // output row group (0..60)
    const int tx4 = (tid & 15) * 4;    // output col group (0..60)

    const int a_m = tid >> 2;          // 0..63
    const int a_k = (tid & 3) * 4;     // 0,4,8,12
    const int b_k = tid >> 4;          // 0..15
    const int b_n = (tid & 15) * 4;    // 0..60

    const float* Xb = X + (size_t)b * CCH * PIX;

    float acc[4][4];
    #pragma unroll
    for (int i = 0; i < 4; i++)
        #pragma unroll
        for (int j = 0; j < 4; j++) acc[i][j] = 0.f;

    for (int kt = 0; kt < CCH; kt += 16) {
        float4 av = *(const float4*)&Wm[(size_t)(m0 + a_m) * CCH + kt + a_k];
        float4 bv = *(const float4*)&Xb[(size_t)(kt + b_k) * PIX + n0 + b_n];
        As[a_m][a_k + 0] = av.x;
        As[a_m][a_k + 1] = av.y;
        As[a_m][a_k + 2] = av.z;
        As[a_m][a_k + 3] = av.w;
        *(float4*)&Bs[b_k][b_n] = bv;
        __syncthreads();

        #pragma unroll
        for (int kk = 0; kk < 16; kk++) {
            float a0 = As[ty4 + 0][kk];
            float a1 = As[ty4 + 1][kk];
            float a2 = As[ty4 + 2][kk];
            float a3 = As[ty4 + 3][kk];
            float4 bb = *(const float4*)&Bs[kk][tx4];
            acc[0][0] += a0 * bb.x; acc[0][1] += a0 * bb.y; acc[0][2] += a0 * bb.z; acc[0][3] += a0 * bb.w;
            acc[1][0] += a1 * bb.x; acc[1][1] += a1 * bb.y; acc[1][2] += a1 * bb.z; acc[1][3] += a1 * bb.w;
            acc[2][0] += a2 * bb.x; acc[2][1] += a2 * bb.y; acc[2][2] += a2 * bb.z; acc[2][3] += a2 * bb.w;
            acc[3][0] += a3 * bb.x; acc[3][1] += a3 * bb.y; acc[3][2] += a3 * bb.z; acc[3][3] += a3 * bb.w;
        }
        __syncthreads();
    }

    float* Fb = F + (size_t)b * CCH * PIX;
    #pragma unroll
    for (int i = 0; i < 4; i++) {
        float4 o = make_float4(acc[i][0], acc[i][1], acc[i][2], acc[i][3]);
        *(float4*)&Fb[(size_t)(m0 + ty4 + i) * PIX + n0 + tx4] = o;
    }
}

// ---------------------------------------------------------------------------
// Kernel 2: per-(b,c) Gram matrix  S[i,j] = sum_h F[h,i] * F[h,j]
// One block per (b,c); F tile (64x64 fp32 = 16KB) in smem; 4x4 microtile.
// ---------------------------------------------------------------------------
__global__ __launch_bounds__(256) void gram_kernel(
    const float* __restrict__ F,   // [B, C, H, W]
    float* __restrict__ S)         // [B, C, W, W]
{
    __shared__ float Fs[64][64];

    const int c = blockIdx.x;
    const int b = blockIdx.y;
    const int tid = threadIdx.x;

    const float* Fp = F + ((size_t)b * CCH + c) * PIX;
    #pragma unroll
    for (int i = tid; i < 1024; i += 256)
        ((float4*)Fs)[i] = ((const float4*)Fp)[i];
    __syncthreads();

    const int i0 = (tid >> 4) * 4;
    const int j0 = (tid & 15) * 4;

    float acc[4][4];
    #pragma unroll
    for (int i = 0; i < 4; i++)
        #pragma unroll
        for (int j = 0; j < 4; j++) acc[i][j] = 0.f;

    #pragma unroll 8
    for (int h = 0; h < 64; h++) {
        float4 a  = *(const float4*)&Fs[h][i0];
        float4 bb = *(const float4*)&Fs[h][j0];
        acc[0][0] += a.x * bb.x; acc[0][1] += a.x * bb.y; acc[0][2] += a.x * bb.z; acc[0][3] += a.x * bb.w;
        acc[1][0] += a.y * bb.x; acc[1][1] += a.y * bb.y; acc[1][2] += a.y * bb.z; acc[1][3] += a.y * bb.w;
        acc[2][0] += a.z * bb.x; acc[2][1] += a.z * bb.y; acc[2][2] += a.z * bb.z; acc[2][3] += a.z * bb.w;
        acc[3][0] += a.w * bb.x; acc[3][1] += a.w * bb.y; acc[3][2] += a.w * bb.z; acc[3][3] += a.w * bb.w;
    }

    float* Sp = S + ((size_t)b * CCH + c) * PIX;
    #pragma unroll
    for (int i = 0; i < 4; i++) {
        float4 o = make_float4(acc[i][0], acc[i][1], acc[i][2], acc[i][3]);
        *(float4*)&Sp[(size_t)(i0 + i) * 64 + j0] = o;
    }
}

// ---------------------------------------------------------------------------
// Kernel 3: channel softmax (axis=1) for both branches + final combine.
// Thread owns one pixel (b,p); online softmax over c, then second pass emits
//   out = f_opt * f_sar * (p_opt * p_sar)^2
// Loads are coalesced (consecutive p across threads at each c).
// ---------------------------------------------------------------------------
__global__ __launch_bounds__(256) void softmax_out_kernel(
    const float* __restrict__ So, const float* __restrict__ Ss,
    const float* __restrict__ Fo, const float* __restrict__ Fs,
    float* __restrict__ out)
{
    const int b = blockIdx.y;
    const int p = blockIdx.x * 256 + threadIdx.x;
    const size_t base = (size_t)b * CCH * PIX + p;

    float mo = -1e30f, sumo = 0.f;
    float ms = -1e30f, sums = 0.f;

    #pragma unroll 4
    for (int c = 0; c < CCH; c++) {
        float vo = So[base + (size_t)c * PIX];
        float vs = Ss[base + (size_t)c * PIX];
        if (vo > mo) { sumo = sumo * __expf(mo - vo) + 1.f; mo = vo; }
        else         { sumo += __expf(vo - mo); }
        if (vs > ms) { sums = sums * __expf(ms - vs) + 1.f; ms = vs; }
        else         { sums += __expf(vs - ms); }
    }

    const float io = 1.f / sumo;
    const float is = 1.f / sums;

    #pragma unroll 4
    for (int c = 0; c < CCH; c++) {
        const size_t idx = base + (size_t)c * PIX;
        float po  = __expf(So[idx] - mo) * io;
        float ps  = __expf(Ss[idx] - ms) * is;
        float had = po * ps;
        out[idx] = Fo[idx] * Fs[idx] * had * had;
    }
}

// ---------------------------------------------------------------------------
extern "C" void kernel_launch(void* const* d_in, const int* in_sizes, int n_in,
                              void* d_out, int out_size)
{
    const float* opt   = (const float*)d_in[0];
    const float* sar   = (const float*)d_in[1];
    const float* W_opt = (const float*)d_in[2];
    const float* W_sar = (const float*)d_in[3];
    float* out = (float*)d_out;

    float *fo, *fs, *so, *ss;
    cudaGetSymbolAddress((void**)&fo, g_fopt);
    cudaGetSymbolAddress((void**)&fs, g_fsar);
    cudaGetSymbolAddress((void**)&so, g_sopt);
    cudaGetSymbolAddress((void**)&ss, g_ssar);

    dim3 gconv(PIX / 64, CCH / 64, BATCH);   // (64, 8, 8)
    conv1x1_kernel<<<gconv, 256>>>(opt, W_opt, fo);
    conv1x1_kernel<<<gconv, 256>>>(sar, W_sar, fs);

    dim3 ggram(CCH, BATCH);                  // (512, 8)
    gram_kernel<<<ggram, 256>>>(fo, so);
    gram_kernel<<<ggram, 256>>>(fs, ss);

    dim3 gsm(PIX / 256, BATCH);              // (16, 8)
    softmax_out_kernel<<<gsm, 256>>>(so, ss, fo, fs, out);
}

// round 8
// speedup vs baseline: 1.7462x; 1.7462x over previous
#include <cuda_runtime.h>
#include <cstdint>

#define BATCH 8
#define CCH   512
#define HH    64
#define PIX   4096
#define NELEM (BATCH * CCH * PIX)       // 16,777,216

// ---------------- scratch (static device globals; no runtime alloc) --------
__device__ float g_F[2][NELEM];          // F_opt, F_sar (fp32 conv outputs)
__device__ float g_T[4][NELEM];          // Xt hi/lo per branch; [0],[2] reused as S_opt,S_sar
__device__ float g_W[4][CCH * CCH];      // Whi_o, Wlo_o, Whi_s, Wlo_s

// ---------------- helpers --------------------------------------------------
__device__ __forceinline__ uint32_t smem_to_u32(const void* p) {
    uint32_t a;
    asm("{ .reg .u64 t; cvta.to.shared.u64 t, %1; cvt.u32.u64 %0, t; }" : "=r"(a) : "l"(p));
    return a;
}
__device__ __forceinline__ float tf32r(float x) {
    uint32_t u;
    asm("cvt.rna.tf32.f32 %0, %1;" : "=r"(u) : "f"(x));
    return __uint_as_float(u);
}
__device__ __forceinline__ void cp16(uint32_t dst, const float* src) {
    asm volatile("cp.async.cg.shared.global [%0], [%1], 16;" :: "r"(dst), "l"(src));
}
#define CP_COMMIT() asm volatile("cp.async.commit_group;" ::: "memory")
#define CP_WAIT(n)  asm volatile("cp.async.wait_group %0;" :: "n"(n) : "memory")

// m16n8k8 tf32 warp MMA (baseline PTX, valid on compute_103)
__device__ __forceinline__ void mma_tf32(float c[4], const uint32_t a[4], const uint32_t b[2]) {
    asm volatile(
        "mma.sync.aligned.m16n8k8.row.col.f32.tf32.tf32.f32 "
        "{%0,%1,%2,%3}, {%4,%5,%6,%7}, {%8,%9}, {%0,%1,%2,%3};\n"
        : "+f"(c[0]), "+f"(c[1]), "+f"(c[2]), "+f"(c[3])
        : "r"(a[0]), "r"(a[1]), "r"(a[2]), "r"(a[3]), "r"(b[0]), "r"(b[1]));
}

// ---------------------------------------------------------------------------
// Prep 1: split W (both branches) into tf32 hi/lo
// ---------------------------------------------------------------------------
__global__ __launch_bounds__(256) void wsplit_kernel(
    const float* __restrict__ Wo, const float* __restrict__ Ws)
{
    int i = blockIdx.x * 256 + threadIdx.x;
    if (i >= CCH * CCH) return;
    float a = Wo[i];
    float h = tf32r(a);
    g_W[0][i] = h;  g_W[1][i] = tf32r(a - h);
    float b = Ws[i];
    h = tf32r(b);
    g_W[2][i] = h;  g_W[3][i] = tf32r(b - h);
}

// ---------------------------------------------------------------------------
// Prep 2: transpose X[b,c,p] -> Xt[b,p,c] with tf32 hi/lo split
// ---------------------------------------------------------------------------
__global__ __launch_bounds__(256) void transpose_split_kernel(
    const float* __restrict__ X, float* __restrict__ Thi, float* __restrict__ Tlo)
{
    __shared__ float t[32][33];
    const int b  = blockIdx.z;
    const int p0 = blockIdx.x * 32;
    const int c0 = blockIdx.y * 32;
    const int tx = threadIdx.x, ty = threadIdx.y;   // 32 x 8

    const float* Xb = X + (size_t)b * CCH * PIX;
    #pragma unroll
    for (int i = 0; i < 4; i++)
        t[ty + 8 * i][tx] = Xb[(size_t)(c0 + ty + 8 * i) * PIX + p0 + tx];
    __syncthreads();

    float* Hb = Thi + (size_t)b * PIX * CCH;
    float* Lb = Tlo + (size_t)b * PIX * CCH;
    #pragma unroll
    for (int i = 0; i < 4; i++) {
        float x  = t[tx][ty + 8 * i];        // t[c_local][p_local]
        float hi = tf32r(x);
        float lo = tf32r(x - hi);
        size_t o = (size_t)(p0 + ty + 8 * i) * CCH + c0 + tx;
        Hb[o] = hi;  Lb[o] = lo;
    }
}

// ---------------------------------------------------------------------------
// Main GEMM: warp-level mma.sync tf32, 3xTF32 accumulation.
//   F[b,m,n] = sum_k W[m,k] * Xt[b,n,k]
// CTA tile 128x128, BK=32, 256 threads = 8 warps (warp tile 64x32).
// k-pair interleave: logical frag col c<4 -> phys 2c, c>=4 -> phys 2c+1,
// applied identically to A and B, so all frag loads are float2 from [row][k].
// ---------------------------------------------------------------------------
#define BM 128
#define BN 128
#define BK 32
#define PADK 40
#define ARRF  (BM * PADK)                // 5120 floats per array
#define BUFF  (4 * ARRF)                 // Ah, Al, Bh, Bl
#define CONV_SMEM (2 * BUFF * 4)         // bytes = 163840

__global__ __launch_bounds__(256) void conv_mma_kernel(
    const float* __restrict__ Thi_o, const float* __restrict__ Tlo_o,
    const float* __restrict__ Thi_s, const float* __restrict__ Tlo_s,
    float* __restrict__ Fo, float* __restrict__ Fs)
{
    extern __shared__ float sm[];
    const uint32_t sb = smem_to_u32(sm);
    const int tid = threadIdx.x;
    const int wid = tid >> 5;
    const int lane = tid & 31;
    const int g = lane >> 2;            // 0..7
    const int t = lane & 3;             // 0..3

    const int n0 = blockIdx.x * BN;
    const int m0 = blockIdx.y * BM;
    const int z  = blockIdx.z;
    const int b  = z >> 1;
    const int br = z & 1;

    const float* Whi = g_W[br ? 2 : 0];
    const float* Wlo = g_W[br ? 3 : 1];
    const float* Xhi = (br ? Thi_s : Thi_o) + (size_t)b * PIX * CCH;
    const float* Xlo = (br ? Tlo_s : Tlo_o) + (size_t)b * PIX * CCH;
    float*       F   = (br ? Fs : Fo) + (size_t)b * CCH * PIX;

    const int wm = (wid & 1) * 64;      // warp m-offset within CTA tile
    const int wn = (wid >> 1) * 32;     // warp n-offset

    float acc[4][4][4];
    #pragma unroll
    for (int mf = 0; mf < 4; mf++)
        #pragma unroll
        for (int nf = 0; nf < 4; nf++)
            #pragma unroll
            for (int q = 0; q < 4; q++) acc[mf][nf][q] = 0.f;

    // --- stage loader: 16 cp.async x16B per thread -------------------------
    auto load_stage = [&](int kt) {
        const int k0 = kt * BK;
        const uint32_t base = sb + (uint32_t)((kt & 1) * BUFF) * 4u;
        #pragma unroll
        for (int i = 0; i < 4; i++) {
            const int id  = tid + i * 256;
            const int row = id >> 3;
            const int c   = (id & 7) * 4;
            const uint32_t doff = (uint32_t)(row * PADK + c) * 4u;
            cp16(base + 0 * ARRF * 4 + doff, Whi + (size_t)(m0 + row) * CCH + k0 + c);
            cp16(base + 1 * ARRF * 4 + doff, Wlo + (size_t)(m0 + row) * CCH + k0 + c);
            cp16(base + 2 * ARRF * 4 + doff, Xhi + (size_t)(n0 + row) * CCH + k0 + c);
            cp16(base + 3 * ARRF * 4 + doff, Xlo + (size_t)(n0 + row) * CCH + k0 + c);
        }
    };

    load_stage(0);
    CP_COMMIT();

    for (int kt = 0; kt < CCH / BK; kt++) {
        if (kt < CCH / BK - 1) { load_stage(kt + 1); CP_COMMIT(); CP_WAIT(1); }
        else                   { CP_WAIT(0); }
        __syncthreads();

        const float* Ah = sm + (kt & 1) * BUFF;
        const float* Al = Ah + ARRF;
        const float* Bh = Ah + 2 * ARRF;
        const float* Bl = Ah + 3 * ARRF;

        #pragma unroll
        for (int s = 0; s < 4; s++) {
            const int kc = s * 8 + 2 * t;         // phys k of logical col t (pair-interleaved)

            uint32_t ah[4][4], al[4][4];
            #pragma unroll
            for (int mf = 0; mf < 4; mf++) {
                const float* p = Ah + (wm + mf * 16 + g) * PADK + kc;
                float2 v0 = *(const float2*)p;
                float2 v1 = *(const float2*)(p + 8 * PADK);
                ah[mf][0] = __float_as_uint(v0.x); ah[mf][2] = __float_as_uint(v0.y);
                ah[mf][1] = __float_as_uint(v1.x); ah[mf][3] = __float_as_uint(v1.y);
                const float* q = Al + (wm + mf * 16 + g) * PADK + kc;
                float2 w0 = *(const float2*)q;
                float2 w1 = *(const float2*)(q + 8 * PADK);
                al[mf][0] = __float_as_uint(w0.x); al[mf][2] = __float_as_uint(w0.y);
                al[mf][1] = __float_as_uint(w1.x); al[mf][3] = __float_as_uint(w1.y);
            }
            uint32_t bh[4][2], bl[4][2];
            #pragma unroll
            for (int nf = 0; nf < 4; nf++) {
                float2 v = *(const float2*)(Bh + (wn + nf * 8 + g) * PADK + kc);
                bh[nf][0] = __float_as_uint(v.x); bh[nf][1] = __float_as_uint(v.y);
                float2 w = *(const float2*)(Bl + (wn + nf * 8 + g) * PADK + kc);
                bl[nf][0] = __float_as_uint(w.x); bl[nf][1] = __float_as_uint(w.y);
            }

            #pragma unroll
            for (int mf = 0; mf < 4; mf++)
                #pragma unroll
                for (int nf = 0; nf < 4; nf++) {
                    mma_tf32(acc[mf][nf], ah[mf], bh[nf]);   // hi*hi
                    mma_tf32(acc[mf][nf], al[mf], bh[nf]);   // lo*hi
                    mma_tf32(acc[mf][nf], ah[mf], bl[nf]);   // hi*lo
                }
        }
        __syncthreads();
    }

    // --- epilogue: c0=(g,2t) c1=(g,2t+1) c2=(g+8,2t) c3=(g+8,2t+1) ---------
    #pragma unroll
    for (int mf = 0; mf < 4; mf++) {
        const int m = m0 + wm + mf * 16 + g;
        #pragma unroll
        for (int nf = 0; nf < 4; nf++) {
            const int col = n0 + wn + nf * 8 + 2 * t;
            *(float2*)&F[(size_t)m * PIX + col] =
                make_float2(acc[mf][nf][0], acc[mf][nf][1]);
            *(float2*)&F[(size_t)(m + 8) * PIX + col] =
                make_float2(acc[mf][nf][2], acc[mf][nf][3]);
        }
    }
}

// ---------------------------------------------------------------------------
// Gram: S[b,c,i,j] = sum_h F[b,c,h,i] * F[b,c,h,j]
// ---------------------------------------------------------------------------
__global__ __launch_bounds__(256) void gram_kernel(
    const float* __restrict__ F, float* __restrict__ S)
{
    __shared__ float Fsh[64][64];
    const int c = blockIdx.x, b = blockIdx.y, tid = threadIdx.x;
    const float* Fp = F + ((size_t)b * CCH + c) * PIX;
    #pragma unroll
    for (int i = tid; i < 1024; i += 256)
        ((float4*)Fsh)[i] = ((const float4*)Fp)[i];
    __syncthreads();

    const int i0 = (tid >> 4) * 4, j0 = (tid & 15) * 4;
    float acc[4][4];
    #pragma unroll
    for (int i = 0; i < 4; i++)
        #pragma unroll
        for (int j = 0; j < 4; j++) acc[i][j] = 0.f;

    #pragma unroll 8
    for (int h = 0; h < 64; h++) {
        float4 a  = *(const float4*)&Fsh[h][i0];
        float4 bb = *(const float4*)&Fsh[h][j0];
        acc[0][0] += a.x * bb.x; acc[0][1] += a.x * bb.y; acc[0][2] += a.x * bb.z; acc[0][3] += a.x * bb.w;
        acc[1][0] += a.y * bb.x; acc[1][1] += a.y * bb.y; acc[1][2] += a.y * bb.z; acc[1][3] += a.y * bb.w;
        acc[2][0] += a.z * bb.x; acc[2][1] += a.z * bb.y; acc[2][2] += a.z * bb.z; acc[2][3] += a.z * bb.w;
        acc[3][0] += a.w * bb.x; acc[3][1] += a.w * bb.y; acc[3][2] += a.w * bb.z; acc[3][3] += a.w * bb.w;
    }
    float* Sp = S + ((size_t)b * CCH + c) * PIX;
    #pragma unroll
    for (int i = 0; i < 4; i++)
        *(float4*)&Sp[(size_t)(i0 + i) * 64 + j0] =
            make_float4(acc[i][0], acc[i][1], acc[i][2], acc[i][3]);
}

// ---------------------------------------------------------------------------
// Softmax over channels (both branches) + final combine
// ---------------------------------------------------------------------------
__global__ __launch_bounds__(256) void softmax_out_kernel(
    const float* __restrict__ So, const float* __restrict__ Ss,
    const float* __restrict__ Fo, const float* __restrict__ Fs,
    float* __restrict__ out)
{
    const int b = blockIdx.y;
    const int p = blockIdx.x * 256 + threadIdx.x;
    const size_t base = (size_t)b * CCH * PIX + p;

    float mo = -1e30f, sumo = 0.f, ms = -1e30f, sums = 0.f;
    #pragma unroll 4
    for (int c = 0; c < CCH; c++) {
        float vo = So[base + (size_t)c * PIX];
        float vs = Ss[base + (size_t)c * PIX];
        if (vo > mo) { sumo = sumo * __expf(mo - vo) + 1.f; mo = vo; }
        else         { sumo += __expf(vo - mo); }
        if (vs > ms) { sums = sums * __expf(ms - vs) + 1.f; ms = vs; }
        else         { sums += __expf(vs - ms); }
    }
    const float io = 1.f / sumo, is = 1.f / sums;
    #pragma unroll 4
    for (int c = 0; c < CCH; c++) {
        const size_t idx = base + (size_t)c * PIX;
        float po  = __expf(So[idx] - mo) * io;
        float ps  = __expf(Ss[idx] - ms) * is;
        float had = po * ps;
        out[idx] = Fo[idx] * Fs[idx] * had * had;
    }
}

// ---------------------------------------------------------------------------
extern "C" void kernel_launch(void* const* d_in, const int* in_sizes, int n_in,
                              void* d_out, int out_size)
{
    const float* opt   = (const float*)d_in[0];
    const float* sar   = (const float*)d_in[1];
    const float* W_opt = (const float*)d_in[2];
    const float* W_sar = (const float*)d_in[3];
    float* out = (float*)d_out;

    float *fF, *fT;
    cudaGetSymbolAddress((void**)&fF, g_F);
    cudaGetSymbolAddress((void**)&fT, g_T);
    float* Fo    = fF;
    float* Fs    = fF + (size_t)NELEM;
    float* Thi_o = fT;
    float* Tlo_o = fT + (size_t)NELEM;
    float* Thi_s = fT + (size_t)2 * NELEM;
    float* Tlo_s = fT + (size_t)3 * NELEM;
    float* So    = Thi_o;   // reuse after conv consumes Xt buffers
    float* Ss    = Thi_s;

    cudaFuncSetAttribute(conv_mma_kernel, cudaFuncAttributeMaxDynamicSharedMemorySize, CONV_SMEM);

    // prep
    wsplit_kernel<<<(CCH * CCH + 255) / 256, 256>>>(W_opt, W_sar);
    dim3 gtr(PIX / 32, CCH / 32, BATCH);
    transpose_split_kernel<<<gtr, dim3(32, 8)>>>(opt, Thi_o, Tlo_o);
    transpose_split_kernel<<<gtr, dim3(32, 8)>>>(sar, Thi_s, Tlo_s);

    // tensor-core conv (both branches, all batches)
    dim3 gconv(PIX / BN, CCH / BM, BATCH * 2);      // (32, 4, 16)
    conv_mma_kernel<<<gconv, 256, CONV_SMEM>>>(Thi_o, Tlo_o, Thi_s, Tlo_s, Fo, Fs);

    // gram + softmax/combine
    dim3 ggram(CCH, BATCH);
    gram_kernel<<<ggram, 256>>>(Fo, So);
    gram_kernel<<<ggram, 256>>>(Fs, Ss);
    dim3 gsm(PIX / 256, BATCH);
    softmax_out_kernel<<<gsm, 256>>>(So, Ss, Fo, Fs, out);
}

// round 11
// speedup vs baseline: 1.8686x; 1.0701x over previous
#include <cuda_runtime.h>
#include <cstdint>

#define BATCH 8
#define CCH   512
#define HH    64
#define PIX   4096
#define NELEM (BATCH * CCH * PIX)       // 16,777,216

// ---------------- scratch (static device globals; no runtime alloc) --------
__device__ float g_F[2][NELEM];          // F_opt, F_sar (fp32 conv outputs)
__device__ float g_S[2][NELEM];          // S_opt, S_sar (gram outputs)
__device__ float g_W[4][CCH * CCH];      // Whi_o, Wlo_o, Whi_s, Wlo_s

// ---------------- helpers --------------------------------------------------
__device__ __forceinline__ uint32_t smem_to_u32(const void* p) {
    uint32_t a;
    asm("{ .reg .u64 t; cvta.to.shared.u64 t, %1; cvt.u32.u64 %0, t; }" : "=r"(a) : "l"(p));
    return a;
}
__device__ __forceinline__ float tf32r(float x) {
    uint32_t u;
    asm("cvt.rna.tf32.f32 %0, %1;" : "=r"(u) : "f"(x));
    return __uint_as_float(u);
}
__device__ __forceinline__ void cp16(uint32_t dst, const float* src) {
    asm volatile("cp.async.cg.shared.global [%0], [%1], 16;" :: "r"(dst), "l"(src));
}
#define CP_COMMIT() asm volatile("cp.async.commit_group;" ::: "memory")
#define CP_WAIT(n)  asm volatile("cp.async.wait_group %0;" :: "n"(n) : "memory")

// m16n8k8 tf32 warp MMA (baseline PTX, valid on compute_103)
__device__ __forceinline__ void mma_tf32(float c[4], const uint32_t a[4], const uint32_t b[2]) {
    asm volatile(
        "mma.sync.aligned.m16n8k8.row.col.f32.tf32.tf32.f32 "
        "{%0,%1,%2,%3}, {%4,%5,%6,%7}, {%8,%9}, {%0,%1,%2,%3};\n"
        : "+f"(c[0]), "+f"(c[1]), "+f"(c[2]), "+f"(c[3])
        : "r"(a[0]), "r"(a[1]), "r"(a[2]), "r"(a[3]), "r"(b[0]), "r"(b[1]));
}

// ---------------------------------------------------------------------------
// Prep: split W (both branches) into tf32 hi/lo
// ---------------------------------------------------------------------------
__global__ __launch_bounds__(256) void wsplit_kernel(
    const float* __restrict__ Wo, const float* __restrict__ Ws)
{
    int i = blockIdx.x * 256 + threadIdx.x;
    if (i >= CCH * CCH) return;
    float a = Wo[i];
    float h = tf32r(a);
    g_W[0][i] = h;  g_W[1][i] = tf32r(a - h);
    float b = Ws[i];
    h = tf32r(b);
    g_W[2][i] = h;  g_W[3][i] = tf32r(b - h);
}

// ---------------------------------------------------------------------------
// Main GEMM: warp-level mma.sync tf32, 3xTF32 accumulation.
//   F[b,m,n] = sum_k W[m,k] * X[b,k,n]
// CTA 128x128, BK=32, 8 warps (warp tile 64x32). A = W hi/lo pre-split in smem
// (K-major). B = RAW X staged in natural [k][n] layout (no transpose kernel);
// hi/lo split happens in registers after LDS; lo fed raw (HW truncates to tf32).
// k-pair interleave: logical frag col c<4 -> phys 2c, c>=4 -> phys 2c+1,
// applied identically to A and B (pure permutation of the contraction index).
// Smem: 2 stages x (Ah + Al + Braw) = 107,520 B -> 2 CTAs/SM.
// ---------------------------------------------------------------------------
#define BM 128
#define BN 128
#define BK 32
#define PADK 36                          // A row pitch (floats)
#define PADN 132                         // B row pitch (floats)
#define A_ARR  (BM * PADK)               // 4608 floats
#define B_ARR  (BK * PADN)               // 4224 floats
#define STAGEF (2 * A_ARR + B_ARR)       // 13440 floats
#define CONV_SMEM (2 * STAGEF * 4)       // 107,520 bytes

__global__ __launch_bounds__(256, 2) void conv_mma_kernel(
    const float* __restrict__ Xopt, const float* __restrict__ Xsar,
    float* __restrict__ Fo, float* __restrict__ Fs)
{
    extern __shared__ float sm[];
    const uint32_t sb = smem_to_u32(sm);
    const int tid = threadIdx.x;
    const int wid = tid >> 5;
    const int lane = tid & 31;
    const int g = lane >> 2;            // 0..7
    const int t = lane & 3;             // 0..3

    const int n0 = blockIdx.x * BN;
    const int m0 = blockIdx.y * BM;
    const int z  = blockIdx.z;
    const int b  = z >> 1;
    const int br = z & 1;

    const float* Whi = g_W[br ? 2 : 0];
    const float* Wlo = g_W[br ? 3 : 1];
    const float* Xr  = (br ? Xsar : Xopt) + (size_t)b * CCH * PIX;
    float*       F   = (br ? Fs : Fo) + (size_t)b * CCH * PIX;

    const int wm = (wid & 1) * 64;      // warp m-offset within CTA tile
    const int wn = (wid >> 1) * 32;     // warp n-offset

    float acc[4][4][4];
    #pragma unroll
    for (int mf = 0; mf < 4; mf++)
        #pragma unroll
        for (int nf = 0; nf < 4; nf++)
            #pragma unroll
            for (int q = 0; q < 4; q++) acc[mf][nf][q] = 0.f;

    // --- stage loader: 12 cp.async x16B per thread -------------------------
    auto load_stage = [&](int kt) {
        const int k0 = kt * BK;
        const uint32_t base = sb + (uint32_t)((kt & 1) * STAGEF) * 4u;
        // A: Whi + Wlo, 128 rows x 32 k (4 chunks each per thread)
        #pragma unroll
        for (int i = 0; i < 4; i++) {
            const int id  = tid + i * 256;
            const int row = id >> 3;
            const int c   = (id & 7) * 4;
            const uint32_t doff = (uint32_t)(row * PADK + c) * 4u;
            const size_t goff = (size_t)(m0 + row) * CCH + k0 + c;
            cp16(base + doff, Whi + goff);
            cp16(base + A_ARR * 4u + doff, Wlo + goff);
        }
        // B: raw X, 32 k-rows x 128 pixels (natural layout, coalesced)
        #pragma unroll
        for (int i = 0; i < 4; i++) {
            const int id = tid + i * 256;
            const int kk = id >> 5;
            const int p  = (id & 31) * 4;
            cp16(base + (uint32_t)(2 * A_ARR + kk * PADN + p) * 4u,
                 Xr + (size_t)(k0 + kk) * PIX + n0 + p);
        }
    };

    load_stage(0);
    CP_COMMIT();

    for (int kt = 0; kt < CCH / BK; kt++) {
        if (kt < CCH / BK - 1) { load_stage(kt + 1); CP_COMMIT(); CP_WAIT(1); }
        else                   { CP_WAIT(0); }
        __syncthreads();

        const float* Ah = sm + (kt & 1) * STAGEF;
        const float* Al = Ah + A_ARR;
        const float* Br = Ah + 2 * A_ARR;

        #pragma unroll
        for (int s = 0; s < 4; s++) {
            const int kc = s * 8 + 2 * t;         // phys k of logical col t

            uint32_t ah[4][4], al[4][4];
            #pragma unroll
            for (int mf = 0; mf < 4; mf++) {
                const float* p = Ah + (wm + mf * 16 + g) * PADK + kc;
                float2 v0 = *(const float2*)p;
                float2 v1 = *(const float2*)(p + 8 * PADK);
                ah[mf][0] = __float_as_uint(v0.x); ah[mf][2] = __float_as_uint(v0.y);
                ah[mf][1] = __float_as_uint(v1.x); ah[mf][3] = __float_as_uint(v1.y);
                const float* q = Al + (wm + mf * 16 + g) * PADK + kc;
                float2 w0 = *(const float2*)q;
                float2 w1 = *(const float2*)(q + 8 * PADK);
                al[mf][0] = __float_as_uint(w0.x); al[mf][2] = __float_as_uint(w0.y);
                al[mf][1] = __float_as_uint(w1.x); al[mf][3] = __float_as_uint(w1.y);
            }
            // B: raw loads + in-register hi/lo split (lo fed raw; HW truncates)
            uint32_t bh[4][2], bl[4][2];
            #pragma unroll
            for (int nf = 0; nf < 4; nf++) {
                const int n = wn + nf * 8 + g;
                float b0 = Br[kc * PADN + n];
                float b1 = Br[(kc + 1) * PADN + n];
                float h0 = tf32r(b0);
                float h1 = tf32r(b1);
                bh[nf][0] = __float_as_uint(h0);
                bh[nf][1] = __float_as_uint(h1);
                bl[nf][0] = __float_as_uint(b0 - h0);
                bl[nf][1] = __float_as_uint(b1 - h1);
            }

            #pragma unroll
            for (int mf = 0; mf < 4; mf++)
                #pragma unroll
                for (int nf = 0; nf < 4; nf++) {
                    mma_tf32(acc[mf][nf], ah[mf], bh[nf]);   // hi*hi
                    mma_tf32(acc[mf][nf], al[mf], bh[nf]);   // lo*hi
                    mma_tf32(acc[mf][nf], ah[mf], bl[nf]);   // hi*lo
                }
        }
        __syncthreads();
    }

    // --- epilogue: c0=(g,2t) c1=(g,2t+1) c2=(g+8,2t) c3=(g+8,2t+1) ---------
    #pragma unroll
    for (int mf = 0; mf < 4; mf++) {
        const int m = m0 + wm + mf * 16 + g;
        #pragma unroll
        for (int nf = 0; nf < 4; nf++) {
            const int col = n0 + wn + nf * 8 + 2 * t;
            *(float2*)&F[(size_t)m * PIX + col] =
                make_float2(acc[mf][nf][0], acc[mf][nf][1]);
            *(float2*)&F[(size_t)(m + 8) * PIX + col] =
                make_float2(acc[mf][nf][2], acc[mf][nf][3]);
        }
    }
}

// ---------------------------------------------------------------------------
// Gram: S[b,c,i,j] = sum_h F[b,c,h,i] * F[b,c,h,j]
// ---------------------------------------------------------------------------
__global__ __launch_bounds__(256) void gram_kernel(
    const float* __restrict__ F, float* __restrict__ S)
{
    __shared__ float Fsh[64][64];
    const int c = blockIdx.x, b = blockIdx.y, tid = threadIdx.x;
    const float* Fp = F + ((size_t)b * CCH + c) * PIX;
    #pragma unroll
    for (int i = tid; i < 1024; i += 256)
        ((float4*)Fsh)[i] = ((const float4*)Fp)[i];
    __syncthreads();

    const int i0 = (tid >> 4) * 4, j0 = (tid & 15) * 4;
    float acc[4][4];
    #pragma unroll
    for (int i = 0; i < 4; i++)
        #pragma unroll
        for (int j = 0; j < 4; j++) acc[i][j] = 0.f;

    #pragma unroll 8
    for (int h = 0; h < 64; h++) {
        float4 a  = *(const float4*)&Fsh[h][i0];
        float4 bb = *(const float4*)&Fsh[h][j0];
        acc[0][0] += a.x * bb.x; acc[0][1] += a.x * bb.y; acc[0][2] += a.x * bb.z; acc[0][3] += a.x * bb.w;
        acc[1][0] += a.y * bb.x; acc[1][1] += a.y * bb.y; acc[1][2] += a.y * bb.z; acc[1][3] += a.y * bb.w;
        acc[2][0] += a.z * bb.x; acc[2][1] += a.z * bb.y; acc[2][2] += a.z * bb.z; acc[2][3] += a.z * bb.w;
        acc[3][0] += a.w * bb.x; acc[3][1] += a.w * bb.y; acc[3][2] += a.w * bb.z; acc[3][3] += a.w * bb.w;
    }
    float* Sp = S + ((size_t)b * CCH + c) * PIX;
    #pragma unroll
    for (int i = 0; i < 4; i++)
        *(float4*)&Sp[(size_t)(i0 + i) * 64 + j0] =
            make_float4(acc[i][0], acc[i][1], acc[i][2], acc[i][3]);
}

// ---------------------------------------------------------------------------
// Softmax over channels (both branches) + final combine
// ---------------------------------------------------------------------------
__global__ __launch_bounds__(256) void softmax_out_kernel(
    const float* __restrict__ So, const float* __restrict__ Ss,
    const float* __restrict__ Fo, const float* __restrict__ Fs,
    float* __restrict__ out)
{
    const int b = blockIdx.y;
    const int p = blockIdx.x * 256 + threadIdx.x;
    const size_t base = (size_t)b * CCH * PIX + p;

    float mo = -1e30f, sumo = 0.f, ms = -1e30f, sums = 0.f;
    #pragma unroll 4
    for (int c = 0; c < CCH; c++) {
        float vo = So[base + (size_t)c * PIX];
        float vs = Ss[base + (size_t)c * PIX];
        if (vo > mo) { sumo = sumo * __expf(mo - vo) + 1.f; mo = vo; }
        else         { sumo += __expf(vo - mo); }
        if (vs > ms) { sums = sums * __expf(ms - vs) + 1.f; ms = vs; }
        else         { sums += __expf(vs - ms); }
    }
    const float io = 1.f / sumo, is = 1.f / sums;
    #pragma unroll 4
    for (int c = 0; c < CCH; c++) {
        const size_t idx = base + (size_t)c * PIX;
        float po  = __expf(So[idx] - mo) * io;
        float ps  = __expf(Ss[idx] - ms) * is;
        float had = po * ps;
        out[idx] = Fo[idx] * Fs[idx] * had * had;
    }
}

// ---------------------------------------------------------------------------
extern "C" void kernel_launch(void* const* d_in, const int* in_sizes, int n_in,
                              void* d_out, int out_size)
{
    const float* opt   = (const float*)d_in[0];
    const float* sar   = (const float*)d_in[1];
    const float* W_opt = (const float*)d_in[2];
    const float* W_sar = (const float*)d_in[3];
    float* out = (float*)d_out;

    float *fF, *fS;
    cudaGetSymbolAddress((void**)&fF, g_F);
    cudaGetSymbolAddress((void**)&fS, g_S);
    float* Fo = fF;
    float* Fs = fF + (size_t)NELEM;
    float* So = fS;
    float* Ss = fS + (size_t)NELEM;

    cudaFuncSetAttribute(conv_mma_kernel, cudaFuncAttributeMaxDynamicSharedMemorySize, CONV_SMEM);

    // prep: W hi/lo split only (X is consumed raw by the conv kernel)
    wsplit_kernel<<<(CCH * CCH + 255) / 256, 256>>>(W_opt, W_sar);

    // tensor-core conv (both branches, all batches)
    dim3 gconv(PIX / BN, CCH / BM, BATCH * 2);      // (32, 4, 16)
    conv_mma_kernel<<<gconv, 256, CONV_SMEM>>>(opt, sar, Fo, Fs);

    // gram + softmax/combine
    dim3 ggram(CCH, BATCH);
    gram_kernel<<<ggram, 256>>>(Fo, So);
    gram_kernel<<<ggram, 256>>>(Fs, Ss);
    dim3 gsm(PIX / 256, BATCH);
    softmax_out_kernel<<<gsm, 256>>>(So, Ss, Fo, Fs, out);
}